// round 1
// baseline (speedup 1.0000x reference)
#include <cuda_runtime.h>

#define HID 8192
#define BATCH 512
#define NIN 16
#define RANK 8
#define NOUT 4

// scratch: u[b][r] = (1/H) * sum_j tanh(h[b][j]) * R[r][j]
__device__ float g_u[BATCH * RANK];

typedef unsigned long long ull;

__device__ __forceinline__ void ffma2(ull& d, ull a, ull b) {
    asm("fma.rn.f32x2 %0, %1, %2, %0;" : "+l"(d) : "l"(a), "l"(b));
}
__device__ __forceinline__ void unpack2(float& lo, float& hi, ull v) {
    asm("mov.b64 {%0, %1}, %2;" : "=f"(lo), "=f"(hi) : "l"(v));
}

// accurate tanh: ~1e-7 abs error, ~6 instrs
__device__ __forceinline__ float fast_tanh(float x) {
    float cx = fminf(fmaxf(x, -15.0f), 15.0f);
    float e = __expf(2.0f * cx);
    return __fdividef(e - 1.0f, e + 1.0f);
}

// ---------------------------------------------------------------------------
// K1: u[b][r] = (1/H) sum_j tanh(h[b][j]) R[r][j]
// grid = 128 blocks (4 batch rows each), 256 threads, full H sweep, float4.
// ---------------------------------------------------------------------------
__global__ void __launch_bounds__(256) k_rank(const float* __restrict__ h,
                                              const float* __restrict__ R) {
    const int t = threadIdx.x;
    const int bbase = blockIdx.x * 4;

    float acc[4][8];
#pragma unroll
    for (int bl = 0; bl < 4; bl++)
#pragma unroll
        for (int r = 0; r < 8; r++) acc[bl][r] = 0.0f;

#pragma unroll
    for (int it = 0; it < 8; it++) {
        const int j = (it * 256 + t) * 4;
        float4 r4[8];
#pragma unroll
        for (int r = 0; r < 8; r++)
            r4[r] = *(const float4*)(R + r * HID + j);
#pragma unroll
        for (int bl = 0; bl < 4; bl++) {
            float4 h4 = *(const float4*)(h + (bbase + bl) * HID + j);
            float t0 = __tanhf(h4.x);
            float t1 = __tanhf(h4.y);
            float t2 = __tanhf(h4.z);
            float t3 = __tanhf(h4.w);
#pragma unroll
            for (int r = 0; r < 8; r++) {
                acc[bl][r] += t0 * r4[r].x;
                acc[bl][r] += t1 * r4[r].y;
                acc[bl][r] += t2 * r4[r].z;
                acc[bl][r] += t3 * r4[r].w;
            }
        }
    }

    // warp reduce all 32 accumulators
#pragma unroll
    for (int bl = 0; bl < 4; bl++)
#pragma unroll
        for (int r = 0; r < 8; r++)
#pragma unroll
            for (int off = 16; off > 0; off >>= 1)
                acc[bl][r] += __shfl_xor_sync(0xffffffffu, acc[bl][r], off);

    __shared__ float red[8][32];
    const int lane = t & 31, w = t >> 5;
    if (lane == 0) {
#pragma unroll
        for (int bl = 0; bl < 4; bl++)
#pragma unroll
            for (int r = 0; r < 8; r++)
                red[w][bl * 8 + r] = acc[bl][r];
    }
    __syncthreads();
    if (t < 32) {
        float s = 0.0f;
#pragma unroll
        for (int w2 = 0; w2 < 8; w2++) s += red[w2][t];
        const int bl = t >> 3, r = t & 7;
        g_u[(bbase + bl) * RANK + r] = s * (1.0f / (float)HID);
    }
}

// ---------------------------------------------------------------------------
// K2: new_h[b][j] = 0.9 h + 0.1 (input[b].W_in[j] + u[b].L[j])
// grid = 128 blocks = j-tiles of 64. Thread owns 4 j-columns, weights in
// registers as f32x2 pairs (pairing over the i/r dimension -> packed operands
// are free bitwise reinterprets of float4 loads). Loop over all 512 b.
// ---------------------------------------------------------------------------
__global__ void __launch_bounds__(256) k_update(const float* __restrict__ input,
                                                const float* __restrict__ hidden,
                                                const float* __restrict__ Win,
                                                const float* __restrict__ L,
                                                float* __restrict__ nh_out) {
    const int t = threadIdx.x;
    const int jg = t & 15;       // 16 groups of 4 j
    const int bs = t >> 4;       // 0..15
    const int j0 = blockIdx.x * 64 + jg * 4;

    // preload weights for 4 j-columns as pairs
    ull wj[4][8];   // W_in[j][0..15] as 8 pairs
    ull lj[4][4];   // L[j][0..7]     as 4 pairs
#pragma unroll
    for (int jj = 0; jj < 4; jj++) {
        const ull* wr = (const ull*)(Win + (j0 + jj) * NIN);
#pragma unroll
        for (int i = 0; i < 8; i++) wj[jj][i] = wr[i];
        const ull* lr = (const ull*)(L + (j0 + jj) * RANK);
#pragma unroll
        for (int r = 0; r < 4; r++) lj[jj][r] = lr[r];
    }

    for (int b = bs; b < BATCH; b += 16) {
        const ull* ip = (const ull*)(input + b * NIN);
        ull ipr[8];
#pragma unroll
        for (int i = 0; i < 8; i++) ipr[i] = ip[i];
        const ull* up = (const ull*)(g_u + b * RANK);
        ull upr[4];
#pragma unroll
        for (int r = 0; r < 4; r++) upr[r] = up[r];

        float4 h4 = *(const float4*)(hidden + b * HID + j0);

        float res[4];
#pragma unroll
        for (int jj = 0; jj < 4; jj++) {
            ull acc = 0ULL;  // (0.0f, 0.0f)
#pragma unroll
            for (int i = 0; i < 8; i++) ffma2(acc, wj[jj][i], ipr[i]);
#pragma unroll
            for (int r = 0; r < 4; r++) ffma2(acc, lj[jj][r], upr[r]);
            float lo, hi;
            unpack2(lo, hi, acc);
            res[jj] = lo + hi;
        }

        float4 o;
        o.x = fmaf(0.1f, res[0], 0.9f * h4.x);
        o.y = fmaf(0.1f, res[1], 0.9f * h4.y);
        o.z = fmaf(0.1f, res[2], 0.9f * h4.z);
        o.w = fmaf(0.1f, res[3], 0.9f * h4.w);
        *(float4*)(nh_out + b * HID + j0) = o;
    }
}

// ---------------------------------------------------------------------------
// K3: out[b][o] = (1/H) sum_j tanh(new_h[b][j]) W_out[o][j]
// grid = 128 blocks (4 batch rows each), accurate tanh, tree reduce.
// ---------------------------------------------------------------------------
__global__ void __launch_bounds__(256) k_out(const float* __restrict__ nh,
                                             const float* __restrict__ Wout,
                                             float* __restrict__ out) {
    const int t = threadIdx.x;
    const int bbase = blockIdx.x * 4;

    float acc[4][4];
#pragma unroll
    for (int bl = 0; bl < 4; bl++)
#pragma unroll
        for (int o = 0; o < 4; o++) acc[bl][o] = 0.0f;

#pragma unroll
    for (int it = 0; it < 8; it++) {
        const int j = (it * 256 + t) * 4;
        float4 w4[4];
#pragma unroll
        for (int o = 0; o < 4; o++)
            w4[o] = *(const float4*)(Wout + o * HID + j);
#pragma unroll
        for (int bl = 0; bl < 4; bl++) {
            float4 x = *(const float4*)(nh + (bbase + bl) * HID + j);
            float t0 = fast_tanh(x.x);
            float t1 = fast_tanh(x.y);
            float t2 = fast_tanh(x.z);
            float t3 = fast_tanh(x.w);
#pragma unroll
            for (int o = 0; o < 4; o++) {
                acc[bl][o] += t0 * w4[o].x;
                acc[bl][o] += t1 * w4[o].y;
                acc[bl][o] += t2 * w4[o].z;
                acc[bl][o] += t3 * w4[o].w;
            }
        }
    }

#pragma unroll
    for (int bl = 0; bl < 4; bl++)
#pragma unroll
        for (int o = 0; o < 4; o++)
#pragma unroll
            for (int off = 16; off > 0; off >>= 1)
                acc[bl][o] += __shfl_xor_sync(0xffffffffu, acc[bl][o], off);

    __shared__ float red[8][16];
    const int lane = t & 31, w = t >> 5;
    if (lane == 0) {
#pragma unroll
        for (int bl = 0; bl < 4; bl++)
#pragma unroll
            for (int o = 0; o < 4; o++)
                red[w][bl * 4 + o] = acc[bl][o];
    }
    __syncthreads();
    if (t < 16) {
        float s = 0.0f;
#pragma unroll
        for (int w2 = 0; w2 < 8; w2++) s += red[w2][t];
        const int bl = t >> 2, o = t & 3;
        out[(bbase + bl) * NOUT + o] = s * (1.0f / (float)HID);
    }
}

extern "C" void kernel_launch(void* const* d_in, const int* in_sizes, int n_in,
                              void* d_out, int out_size) {
    const float* input  = (const float*)d_in[0];  // [512,16]
    const float* hidden = (const float*)d_in[1];  // [512,8192]
    const float* Win    = (const float*)d_in[2];  // [8192,16]
    const float* L      = (const float*)d_in[3];  // [8192,8]
    const float* R      = (const float*)d_in[4];  // [8,8192]
    const float* Wout   = (const float*)d_in[5];  // [4,8192]

    float* out = (float*)d_out;                   // [512,4] then [512,8192]
    float* nh  = out + BATCH * NOUT;

    k_rank<<<BATCH / 4, 256>>>(hidden, R);
    k_update<<<HID / 64, 256>>>(input, hidden, Win, L, nh);
    k_out<<<BATCH / 4, 256>>>(nh, Wout, out);
}